// round 6
// baseline (speedup 1.0000x reference)
#include <cuda_runtime.h>

#define NQ    4
#define CIN   64
#define HH    64
#define WW    64
#define OUTC  128
#define TH    16
#define TW    16
#define NTHR  128
#define HALO_H (TH + 2)
#define HALO_W (TW + 2)
#define HALO_N (HALO_H * HALO_W)   // 324

// Fixed gate matrices: [0..31] = U3 per wire, [32..63] = CU3 per wire.
__device__ float g_gates[64];
// Conv weights pre-packed for f32x2 channel-pair accumulation:
// index ((s*9+tap)*4+p)*2+h  ->  (w[c0][oa], w[c1][oa], w[c0][ob], w[c1][ob])
__device__ float4 g_wpack[576];

#define FMA2(acc, a, b) \
    asm("fma.rn.f32x2 %0, %1, %2, %0;" : "+l"(acc) : "l"(a), "l"(b))
#define FMA2N(d, a, b, c) \
    asm("fma.rn.f32x2 %0, %1, %2, %3;" : "=l"(d) : "l"(a), "l"(b), "l"(c))
#define PACK2(d, lo, hi) \
    asm("mov.b64 %0, {%1, %2};" : "=l"(d) : "f"(lo), "f"(hi))

__global__ void init_kernel(const float* __restrict__ fc1w,
                            const float* __restrict__ u3p,
                            const float* __restrict__ cu3p)
{
    int i = threadIdx.x;
    if (i < 8) {
        const float* p = (i < 4) ? (u3p + i * 3) : (cu3p + (i - 4) * 3);
        float th = p[0], ph = p[1], la = p[2];
        float st, ct;   sincosf(0.5f * th, &st, &ct);
        float sl, cl;   sincosf(la, &sl, &cl);
        float sp, cp;   sincosf(ph, &sp, &cp);
        float spl, cpl; sincosf(ph + la, &spl, &cpl);
        float* o = g_gates + i * 8;
        o[0] = ct;        o[1] = 0.f;
        o[2] = -cl * st;  o[3] = -sl * st;
        o[4] = cp * st;   o[5] = sp * st;
        o[6] = cpl * ct;  o[7] = spl * ct;
    }
    {
        int h   = i & 1;
        int p   = (i >> 1) & 3;
        int tap = (i >> 3) % 9;
        int s   = i / 72;
        int c0  = s * 8 + 2 * p;
        int c1  = c0 + 1;
        int oa  = 2 * h, ob = 2 * h + 1;
        g_wpack[i] = make_float4(fc1w[oa * 576 + c0 * 9 + tap],
                                 fc1w[oa * 576 + c1 * 9 + tap],
                                 fc1w[ob * 576 + c0 * 9 + tap],
                                 fc1w[ob * 576 + c1 * 9 + tap]);
    }
}

// Full 4-qubit circuit from the 4 angles -> <Z> per wire.
__device__ __forceinline__ float4 quantum_ez(float a0, float a1, float a2, float a3)
{
    float S[NQ][4];
    float angs[NQ] = {a0, a1, a2, a3};
    #pragma unroll
    for (int q = 0; q < NQ; ++q) {
        float st, ct;
        __sincosf(0.5f * angs[q], &st, &ct);
        const float* m = g_gates + q * 8;
        S[q][0] = m[0] * ct + m[2] * st;
        S[q][1] = m[1] * ct + m[3] * st;
        S[q][2] = m[4] * ct + m[6] * st;
        S[q][3] = m[5] * ct + m[7] * st;
    }

    float q01r[4], q01i[4], q23r[4], q23i[4];
    #pragma unroll
    for (int i0 = 0; i0 < 2; ++i0)
        #pragma unroll
        for (int i1 = 0; i1 < 2; ++i1) {
            float xr = S[0][i0 * 2], xi = S[0][i0 * 2 + 1];
            float yr = S[1][i1 * 2], yi = S[1][i1 * 2 + 1];
            q01r[i0 * 2 + i1] = xr * yr - xi * yi;
            q01i[i0 * 2 + i1] = xr * yi + xi * yr;
            xr = S[2][i0 * 2]; xi = S[2][i0 * 2 + 1];
            yr = S[3][i1 * 2]; yi = S[3][i1 * 2 + 1];
            q23r[i0 * 2 + i1] = xr * yr - xi * yi;
            q23i[i0 * 2 + i1] = xr * yi + xi * yr;
        }

    float pr[16], pi[16];
    #pragma unroll
    for (int u = 0; u < 4; ++u)
        #pragma unroll
        for (int v = 0; v < 4; ++v) {
            pr[u * 4 + v] = q01r[u] * q23r[v] - q01i[u] * q23i[v];
            pi[u * 4 + v] = q01r[u] * q23i[v] + q01i[u] * q23r[v];
        }

    #pragma unroll
    for (int g = 0; g < 4; ++g) {
        const float* U = g_gates + 32 + g * 8;
        float u00r = U[0], u00i = U[1], u01r = U[2], u01i = U[3];
        float u10r = U[4], u10i = U[5], u11r = U[6], u11i = U[7];
        const int bc = 8 >> g;
        const int bt = 8 >> ((g + 1) & 3);
        #pragma unroll
        for (int i = 0; i < 16; ++i) {
            if ((i & bc) && !(i & bt)) {
                const int j = i | bt;
                float x0r = pr[i], x0i = pi[i], x1r = pr[j], x1i = pi[j];
                pr[i] = u00r * x0r - u00i * x0i + u01r * x1r - u01i * x1i;
                pi[i] = u00r * x0i + u00i * x0r + u01r * x1i + u01i * x1r;
                pr[j] = u10r * x0r - u10i * x0i + u11r * x1r - u11i * x1i;
                pi[j] = u10r * x0i + u10i * x0r + u11r * x1i + u11i * x1r;
            }
        }
    }

    float e0 = 0.f, e1 = 0.f, e2 = 0.f, e3 = 0.f;
    #pragma unroll
    for (int i = 0; i < 16; ++i) {
        float pp = pr[i] * pr[i] + pi[i] * pi[i];
        e0 += (i & 8) ? -pp : pp;
        e1 += (i & 4) ? -pp : pp;
        e2 += (i & 2) ? -pp : pp;
        e3 += (i & 1) ? -pp : pp;
    }
    return make_float4(e0, e1, e2, e3);
}

__global__ __launch_bounds__(NTHR, 2)
void qconv_kernel(const float* __restrict__ x,     // (16,64,64,64)
                  const float* __restrict__ fc1b,  // (4,)
                  const float* __restrict__ fcw,   // (128,4)
                  const float* __restrict__ fcb,   // (128,)
                  float* __restrict__ out)         // (16,4096,128) flat
{
    __shared__ float4 wq[576];            // packed weights (f32x2 pairs)
    __shared__ float4 xs4[2][2][HALO_N];  // [buf][chan-group][pos] 4 channels/float4
    __shared__ float4 ez[TH * TW];        // 256 pixels

    const int t  = threadIdx.x;
    const int b  = blockIdx.z;
    const int h0 = blockIdx.y * TH;
    const int w0 = blockIdx.x * TW;

    #pragma unroll
    for (int f = t; f < 576; f += NTHR)
        wq[f] = g_wpack[f];

    const int ty = t >> 4;   // 0..7  (handles pixel rows 2ty, 2ty+1)
    const int tx = t & 15;   // 0..15
    const int by = h0 - 1, bx = w0 - 1;

    // ---- channel-invariant halo staging: 3 slots/thread over 324 positions ----
    const int i0 = t, i1 = t + NTHR, i2 = t + 2 * NTHR;
    const bool has2 = (i2 < HALO_N);
    const int r0 = i0 / HALO_W, c0s = i0 - r0 * HALO_W;
    const int r1 = i1 / HALO_W, c1s = i1 - r1 * HALO_W;
    const int r2 = has2 ? i2 / HALO_W : 0, c2s = has2 ? (i2 - r2 * HALO_W) : 0;

    int gy, gx;
    gy = by + r0; gx = bx + c0s;
    const bool va0 = (unsigned)gy < (unsigned)HH && (unsigned)gx < (unsigned)WW;
    const float* cur0 = x + ((size_t)b * CIN) * (HH * WW) + (va0 ? gy * WW + gx : 0);
    gy = by + r1; gx = bx + c1s;
    const bool va1 = (unsigned)gy < (unsigned)HH && (unsigned)gx < (unsigned)WW;
    const float* cur1 = x + ((size_t)b * CIN) * (HH * WW) + (va1 ? gy * WW + gx : 0);
    gy = by + r2; gx = bx + c2s;
    const bool va2 = has2 && (unsigned)gy < (unsigned)HH && (unsigned)gx < (unsigned)WW;
    const float* cur2 = x + ((size_t)b * CIN) * (HH * WW) + (va2 ? gy * WW + gx : 0);

    // Prologue: load channel-group 0 into registers.
    float v0[8], v1[8], v2[8];
    #pragma unroll
    for (int k = 0; k < 8; ++k) v0[k] = va0 ? cur0[k * (HH * WW)] : 0.f;
    #pragma unroll
    for (int k = 0; k < 8; ++k) v1[k] = va1 ? cur1[k * (HH * WW)] : 0.f;
    #pragma unroll
    for (int k = 0; k < 8; ++k) v2[k] = va2 ? cur2[k * (HH * WW)] : 0.f;
    cur0 += 8 * HH * WW; cur1 += 8 * HH * WW; cur2 += 8 * HH * WW;

    // 8 packed accumulators: A = pixel row 2ty, B = pixel row 2ty+1.
    unsigned long long A0, A1, A2, A3, B0, B1, B2, B3;
    {
        float z = 0.f;
        float b0 = fc1b[0], b1 = fc1b[1], b2 = fc1b[2], b3 = fc1b[3];
        PACK2(A0, b0, z); PACK2(A1, b1, z); PACK2(A2, b2, z); PACK2(A3, b3, z);
        PACK2(B0, b0, z); PACK2(B1, b1, z); PACK2(B2, b2, z); PACK2(B3, b3, z);
    }

    // Single-barrier-per-stage double-buffered loop:
    //   STS(s) -> [LDG(s+1)] -> barrier -> compute(s)
    // Safe: readers of buf[s&1] (compute(s-2)) finished before any warp could
    // pass barrier(s-1), which precedes STS(s) in program order.
    for (int s = 0; s < 8; ++s) {
        {
            float4* d0 = xs4[s & 1][0];
            float4* d1 = xs4[s & 1][1];
            d0[i0] = make_float4(v0[0], v0[1], v0[2], v0[3]);
            d1[i0] = make_float4(v0[4], v0[5], v0[6], v0[7]);
            d0[i1] = make_float4(v1[0], v1[1], v1[2], v1[3]);
            d1[i1] = make_float4(v1[4], v1[5], v1[6], v1[7]);
            if (has2) {
                d0[i2] = make_float4(v2[0], v2[1], v2[2], v2[3]);
                d1[i2] = make_float4(v2[4], v2[5], v2[6], v2[7]);
            }
        }
        if (s < 7) {
            #pragma unroll
            for (int k = 0; k < 8; ++k) v0[k] = va0 ? cur0[k * (HH * WW)] : 0.f;
            #pragma unroll
            for (int k = 0; k < 8; ++k) v1[k] = va1 ? cur1[k * (HH * WW)] : 0.f;
            #pragma unroll
            for (int k = 0; k < 8; ++k) v2[k] = va2 ? cur2[k * (HH * WW)] : 0.f;
            cur0 += 8 * HH * WW; cur1 += 8 * HH * WW; cur2 += 8 * HH * WW;
        }
        __syncthreads();

        const ulonglong2* xg0 = (const ulonglong2*)xs4[s & 1][0];
        const ulonglong2* xg1 = (const ulonglong2*)xs4[s & 1][1];
        const ulonglong2* wp  = (const ulonglong2*)(wq + s * 72);

        #pragma unroll
        for (int dj = 0; dj < 3; ++dj) {
            // Batch the 8 shared loads for this column before any FMA2 use.
            ulonglong2 xlo[4], xhi[4];
            #pragma unroll
            for (int r = 0; r < 4; ++r)
                xlo[r] = xg0[(2 * ty + r) * HALO_W + tx + dj];
            #pragma unroll
            for (int r = 0; r < 4; ++r)
                xhi[r] = xg1[(2 * ty + r) * HALO_W + tx + dj];
            #pragma unroll
            for (int di = 0; di < 3; ++di) {
                const ulonglong2* wt = wp + (di * 3 + dj) * 8;
                ulonglong2 w0 = wt[0], w1 = wt[1], w2 = wt[2], w3 = wt[3];
                ulonglong2 w4 = wt[4], w5 = wt[5], w6 = wt[6], w7 = wt[7];
                FMA2(A0, xlo[di].x, w0.x); FMA2(A1, xlo[di].x, w0.y);
                FMA2(A2, xlo[di].x, w1.x); FMA2(A3, xlo[di].x, w1.y);
                FMA2(B0, xlo[di+1].x, w0.x); FMA2(B1, xlo[di+1].x, w0.y);
                FMA2(B2, xlo[di+1].x, w1.x); FMA2(B3, xlo[di+1].x, w1.y);
                FMA2(A0, xlo[di].y, w2.x); FMA2(A1, xlo[di].y, w2.y);
                FMA2(A2, xlo[di].y, w3.x); FMA2(A3, xlo[di].y, w3.y);
                FMA2(B0, xlo[di+1].y, w2.x); FMA2(B1, xlo[di+1].y, w2.y);
                FMA2(B2, xlo[di+1].y, w3.x); FMA2(B3, xlo[di+1].y, w3.y);
                FMA2(A0, xhi[di].x, w4.x); FMA2(A1, xhi[di].x, w4.y);
                FMA2(A2, xhi[di].x, w5.x); FMA2(A3, xhi[di].x, w5.y);
                FMA2(B0, xhi[di+1].x, w4.x); FMA2(B1, xhi[di+1].x, w4.y);
                FMA2(B2, xhi[di+1].x, w5.x); FMA2(B3, xhi[di+1].x, w5.y);
                FMA2(A0, xhi[di].y, w6.x); FMA2(A1, xhi[di].y, w6.y);
                FMA2(A2, xhi[di].y, w7.x); FMA2(A3, xhi[di].y, w7.y);
                FMA2(B0, xhi[di+1].y, w6.x); FMA2(B1, xhi[di+1].y, w6.y);
                FMA2(B2, xhi[di+1].y, w7.x); FMA2(B3, xhi[di+1].y, w7.y);
            }
        }
    }

    // Reduce packed accumulators -> angles, run circuit for both pixels.
    {
        float lo, hi, a0, a1, a2, a3;
        asm("mov.b64 {%0, %1}, %2;" : "=f"(lo), "=f"(hi) : "l"(A0)); a0 = lo + hi;
        asm("mov.b64 {%0, %1}, %2;" : "=f"(lo), "=f"(hi) : "l"(A1)); a1 = lo + hi;
        asm("mov.b64 {%0, %1}, %2;" : "=f"(lo), "=f"(hi) : "l"(A2)); a2 = lo + hi;
        asm("mov.b64 {%0, %1}, %2;" : "=f"(lo), "=f"(hi) : "l"(A3)); a3 = lo + hi;
        ez[(2 * ty) * TW + tx] = quantum_ez(a0, a1, a2, a3);
        asm("mov.b64 {%0, %1}, %2;" : "=f"(lo), "=f"(hi) : "l"(B0)); a0 = lo + hi;
        asm("mov.b64 {%0, %1}, %2;" : "=f"(lo), "=f"(hi) : "l"(B1)); a1 = lo + hi;
        asm("mov.b64 {%0, %1}, %2;" : "=f"(lo), "=f"(hi) : "l"(B2)); a2 = lo + hi;
        asm("mov.b64 {%0, %1}, %2;" : "=f"(lo), "=f"(hi) : "l"(B3)); a3 = lo + hi;
        ez[(2 * ty + 1) * TW + tx] = quantum_ez(a0, a1, a2, a3);
    }
    __syncthreads();

    // ---------------- coalesced FC epilogue (f32x2-packed) ----------------
    // Warp wi handles pixels wi*64..wi*64+63; lane k owns channels 4k..4k+3.
    // Pack output-channel pairs: acc01 = (o[4k],o[4k+1]), acc23 = (o[4k+2],o[4k+3]).
    const int lane = t & 31;
    const int wi   = t >> 5;
    const float4* fw4 = (const float4*)fcw;
    float4 fr0 = fw4[4 * lane + 0];   // fcw row c0: weights for e0..e3
    float4 fr1 = fw4[4 * lane + 1];
    float4 fr2 = fw4[4 * lane + 2];
    float4 fr3 = fw4[4 * lane + 3];
    float4 bb4 = ((const float4*)fcb)[lane];

    unsigned long long w01k0, w01k1, w01k2, w01k3;  // (fcw[c0][k], fcw[c1][k])
    unsigned long long w23k0, w23k1, w23k2, w23k3;
    unsigned long long bias01, bias23;
    PACK2(w01k0, fr0.x, fr1.x); PACK2(w01k1, fr0.y, fr1.y);
    PACK2(w01k2, fr0.z, fr1.z); PACK2(w01k3, fr0.w, fr1.w);
    PACK2(w23k0, fr2.x, fr3.x); PACK2(w23k1, fr2.y, fr3.y);
    PACK2(w23k2, fr2.z, fr3.z); PACK2(w23k3, fr2.w, fr3.w);
    PACK2(bias01, bb4.x, bb4.y); PACK2(bias23, bb4.z, bb4.w);

    ulonglong2* ob = (ulonglong2*)out + (size_t)b * 4096 * 32;
    #pragma unroll 4
    for (int j = 0; j < 64; ++j) {
        const int lp = wi * 64 + j;
        float4 e = ez[lp];
        unsigned long long e0p, e1p, e2p, e3p;
        PACK2(e0p, e.x, e.x); PACK2(e1p, e.y, e.y);
        PACK2(e2p, e.z, e.z); PACK2(e3p, e.w, e.w);
        unsigned long long acc01, acc23;
        FMA2N(acc01, w01k0, e0p, bias01);
        FMA2N(acc23, w23k0, e0p, bias23);
        FMA2(acc01, w01k1, e1p); FMA2(acc23, w23k1, e1p);
        FMA2(acc01, w01k2, e2p); FMA2(acc23, w23k2, e2p);
        FMA2(acc01, w01k3, e3p); FMA2(acc23, w23k3, e3p);
        const int py = h0 + (lp >> 4);
        const int px = w0 + (lp & 15);
        ulonglong2 o2; o2.x = acc01; o2.y = acc23;
        ob[(size_t)(py * WW + px) * 32 + lane] = o2;
    }
}

extern "C" void kernel_launch(void* const* d_in, const int* in_sizes, int n_in,
                              void* d_out, int out_size)
{
    (void)in_sizes; (void)n_in; (void)out_size;
    const float* x    = (const float*)d_in[0];
    const float* fc1w = (const float*)d_in[1];
    const float* fc1b = (const float*)d_in[2];
    const float* u3p  = (const float*)d_in[3];
    const float* cu3p = (const float*)d_in[4];
    const float* fcw  = (const float*)d_in[5];
    const float* fcb  = (const float*)d_in[6];
    float* out = (float*)d_out;

    init_kernel<<<1, 576>>>(fc1w, u3p, cu3p);
    dim3 grid(WW / TW, HH / TH, 16);
    qconv_kernel<<<grid, NTHR>>>(x, fc1b, fcw, fcb, out);
}

// round 7
// speedup vs baseline: 1.0875x; 1.0875x over previous
#include <cuda_runtime.h>

#define NQ    4
#define CIN   64
#define HH    64
#define WW    64
#define OUTC  128
#define TH    16
#define TW    16
#define NTHR  128
#define HALO_H (TH + 2)
#define HALO_W (TW + 2)
#define HALO_N (HALO_H * HALO_W)   // 324

#define FMA2(acc, a, b) \
    asm("fma.rn.f32x2 %0, %1, %2, %0;" : "+l"(acc) : "l"(a), "l"(b))
#define FMA2N(d, a, b, c) \
    asm("fma.rn.f32x2 %0, %1, %2, %3;" : "=l"(d) : "l"(a), "l"(b), "l"(c))
#define PACK2(d, lo, hi) \
    asm("mov.b64 %0, {%1, %2};" : "=l"(d) : "f"(lo), "f"(hi))

// Full 4-qubit circuit from the 4 angles -> <Z> per wire. Gates in smem.
__device__ __forceinline__ float4 quantum_ez(const float* __restrict__ sg,
                                             float a0, float a1, float a2, float a3)
{
    float S[NQ][4];
    float angs[NQ] = {a0, a1, a2, a3};
    #pragma unroll
    for (int q = 0; q < NQ; ++q) {
        float st, ct;
        __sincosf(0.5f * angs[q], &st, &ct);
        const float* m = sg + q * 8;
        S[q][0] = m[0] * ct + m[2] * st;
        S[q][1] = m[1] * ct + m[3] * st;
        S[q][2] = m[4] * ct + m[6] * st;
        S[q][3] = m[5] * ct + m[7] * st;
    }

    float q01r[4], q01i[4], q23r[4], q23i[4];
    #pragma unroll
    for (int i0 = 0; i0 < 2; ++i0)
        #pragma unroll
        for (int i1 = 0; i1 < 2; ++i1) {
            float xr = S[0][i0 * 2], xi = S[0][i0 * 2 + 1];
            float yr = S[1][i1 * 2], yi = S[1][i1 * 2 + 1];
            q01r[i0 * 2 + i1] = xr * yr - xi * yi;
            q01i[i0 * 2 + i1] = xr * yi + xi * yr;
            xr = S[2][i0 * 2]; xi = S[2][i0 * 2 + 1];
            yr = S[3][i1 * 2]; yi = S[3][i1 * 2 + 1];
            q23r[i0 * 2 + i1] = xr * yr - xi * yi;
            q23i[i0 * 2 + i1] = xr * yi + xi * yr;
        }

    float pr[16], pi[16];
    #pragma unroll
    for (int u = 0; u < 4; ++u)
        #pragma unroll
        for (int v = 0; v < 4; ++v) {
            pr[u * 4 + v] = q01r[u] * q23r[v] - q01i[u] * q23i[v];
            pi[u * 4 + v] = q01r[u] * q23i[v] + q01i[u] * q23r[v];
        }

    #pragma unroll
    for (int g = 0; g < 4; ++g) {
        const float* U = sg + 32 + g * 8;
        float u00r = U[0], u00i = U[1], u01r = U[2], u01i = U[3];
        float u10r = U[4], u10i = U[5], u11r = U[6], u11i = U[7];
        const int bc = 8 >> g;
        const int bt = 8 >> ((g + 1) & 3);
        #pragma unroll
        for (int i = 0; i < 16; ++i) {
            if ((i & bc) && !(i & bt)) {
                const int j = i | bt;
                float x0r = pr[i], x0i = pi[i], x1r = pr[j], x1i = pi[j];
                pr[i] = u00r * x0r - u00i * x0i + u01r * x1r - u01i * x1i;
                pi[i] = u00r * x0i + u00i * x0r + u01r * x1i + u01i * x1r;
                pr[j] = u10r * x0r - u10i * x0i + u11r * x1r - u11i * x1i;
                pi[j] = u10r * x0i + u10i * x0r + u11r * x1i + u11i * x1r;
            }
        }
    }

    float e0 = 0.f, e1 = 0.f, e2 = 0.f, e3 = 0.f;
    #pragma unroll
    for (int i = 0; i < 16; ++i) {
        float pp = pr[i] * pr[i] + pi[i] * pi[i];
        e0 += (i & 8) ? -pp : pp;
        e1 += (i & 4) ? -pp : pp;
        e2 += (i & 2) ? -pp : pp;
        e3 += (i & 1) ? -pp : pp;
    }
    return make_float4(e0, e1, e2, e3);
}

__global__ __launch_bounds__(NTHR, 2)
void qconv_kernel(const float* __restrict__ x,     // (16,64,64,64)
                  const float* __restrict__ fc1w,  // (4,576)
                  const float* __restrict__ fc1b,  // (4,)
                  const float* __restrict__ u3p,   // (4,3)
                  const float* __restrict__ cu3p,  // (4,3)
                  const float* __restrict__ fcw,   // (128,4)
                  const float* __restrict__ fcb,   // (128,)
                  float* __restrict__ out)         // (16,4096,128) flat
{
    __shared__ float4 wq[576];            // packed conv weights (f32x2 pairs)
    __shared__ float4 xs4[2][2][HALO_N];  // [buf][chan-group][pos] 4 channels/float4
    __shared__ float4 ezd[TH * TW * 2];   // duplicated <Z>: (e0,e0,e1,e1)(e2,e2,e3,e3)
    __shared__ float  sgates[64];         // [0..31] U3, [32..63] CU3

    const int t  = threadIdx.x;
    const int b  = blockIdx.z;
    const int h0 = blockIdx.y * TH;
    const int w0 = blockIdx.x * TW;

    // ---- per-block setup (replaces the init kernel) ----
    if (t < 8) {
        const float* p = (t < 4) ? (u3p + t * 3) : (cu3p + (t - 4) * 3);
        float th = p[0], ph = p[1], la = p[2];
        float st, ct;   __sincosf(0.5f * th, &st, &ct);
        float sl, cl;   __sincosf(la, &sl, &cl);
        float sp, cp;   __sincosf(ph, &sp, &cp);
        float spl, cpl; __sincosf(ph + la, &spl, &cpl);
        float* o = sgates + t * 8;
        o[0] = ct;        o[1] = 0.f;
        o[2] = -cl * st;  o[3] = -sl * st;
        o[4] = cp * st;   o[5] = sp * st;
        o[6] = cpl * ct;  o[7] = spl * ct;
    }
    // Packed weight table: wq[s*72 + tap*8 + p*2 + h] =
    //   (w[c0][2h], w[c1][2h], w[c0][2h+1], w[c1][2h+1]), c0 = s*8+2p.
    #pragma unroll
    for (int f = t; f < 576; f += NTHR) {
        int h   = f & 1;
        int p   = (f >> 1) & 3;
        int tap = (f >> 3) % 9;
        int s   = f / 72;
        int c0  = s * 8 + 2 * p;
        int oa  = 2 * h, ob = 2 * h + 1;
        wq[f] = make_float4(fc1w[oa * 576 + c0 * 9 + tap],
                            fc1w[oa * 576 + (c0 + 1) * 9 + tap],
                            fc1w[ob * 576 + c0 * 9 + tap],
                            fc1w[ob * 576 + (c0 + 1) * 9 + tap]);
    }

    const int ty = t >> 4;   // 0..7  (handles pixel rows 2ty, 2ty+1)
    const int tx = t & 15;   // 0..15
    const int by = h0 - 1, bx = w0 - 1;

    // ---- channel-invariant halo staging: 3 slots/thread over 324 positions ----
    const int i0 = t, i1 = t + NTHR, i2 = t + 2 * NTHR;
    const bool has2 = (i2 < HALO_N);
    const int r0 = i0 / HALO_W, c0s = i0 - r0 * HALO_W;
    const int r1 = i1 / HALO_W, c1s = i1 - r1 * HALO_W;
    const int r2 = has2 ? i2 / HALO_W : 0, c2s = has2 ? (i2 - r2 * HALO_W) : 0;

    int gy, gx;
    gy = by + r0; gx = bx + c0s;
    const bool va0 = (unsigned)gy < (unsigned)HH && (unsigned)gx < (unsigned)WW;
    const float* cur0 = x + ((size_t)b * CIN) * (HH * WW) + (va0 ? gy * WW + gx : 0);
    gy = by + r1; gx = bx + c1s;
    const bool va1 = (unsigned)gy < (unsigned)HH && (unsigned)gx < (unsigned)WW;
    const float* cur1 = x + ((size_t)b * CIN) * (HH * WW) + (va1 ? gy * WW + gx : 0);
    gy = by + r2; gx = bx + c2s;
    const bool va2 = has2 && (unsigned)gy < (unsigned)HH && (unsigned)gx < (unsigned)WW;
    const float* cur2 = x + ((size_t)b * CIN) * (HH * WW) + (va2 ? gy * WW + gx : 0);

    // Prologue: load channel-group 0 into registers.
    float v0[8], v1[8], v2[8];
    #pragma unroll
    for (int k = 0; k < 8; ++k) v0[k] = va0 ? cur0[k * (HH * WW)] : 0.f;
    #pragma unroll
    for (int k = 0; k < 8; ++k) v1[k] = va1 ? cur1[k * (HH * WW)] : 0.f;
    #pragma unroll
    for (int k = 0; k < 8; ++k) v2[k] = va2 ? cur2[k * (HH * WW)] : 0.f;
    cur0 += 8 * HH * WW; cur1 += 8 * HH * WW; cur2 += 8 * HH * WW;

    // 8 packed accumulators: A = pixel row 2ty, B = pixel row 2ty+1.
    unsigned long long A0, A1, A2, A3, B0, B1, B2, B3;
    {
        float z = 0.f;
        float b0 = fc1b[0], b1 = fc1b[1], b2 = fc1b[2], b3 = fc1b[3];
        PACK2(A0, b0, z); PACK2(A1, b1, z); PACK2(A2, b2, z); PACK2(A3, b3, z);
        PACK2(B0, b0, z); PACK2(B1, b1, z); PACK2(B2, b2, z); PACK2(B3, b3, z);
    }

    // Single-barrier-per-stage double-buffered loop:
    //   STS(s) -> [LDG(s+1)] -> barrier -> compute(s)
    for (int s = 0; s < 8; ++s) {
        {
            float4* d0 = xs4[s & 1][0];
            float4* d1 = xs4[s & 1][1];
            d0[i0] = make_float4(v0[0], v0[1], v0[2], v0[3]);
            d1[i0] = make_float4(v0[4], v0[5], v0[6], v0[7]);
            d0[i1] = make_float4(v1[0], v1[1], v1[2], v1[3]);
            d1[i1] = make_float4(v1[4], v1[5], v1[6], v1[7]);
            if (has2) {
                d0[i2] = make_float4(v2[0], v2[1], v2[2], v2[3]);
                d1[i2] = make_float4(v2[4], v2[5], v2[6], v2[7]);
            }
        }
        if (s < 7) {
            #pragma unroll
            for (int k = 0; k < 8; ++k) v0[k] = va0 ? cur0[k * (HH * WW)] : 0.f;
            #pragma unroll
            for (int k = 0; k < 8; ++k) v1[k] = va1 ? cur1[k * (HH * WW)] : 0.f;
            #pragma unroll
            for (int k = 0; k < 8; ++k) v2[k] = va2 ? cur2[k * (HH * WW)] : 0.f;
            cur0 += 8 * HH * WW; cur1 += 8 * HH * WW; cur2 += 8 * HH * WW;
        }
        __syncthreads();

        const ulonglong2* xg0 = (const ulonglong2*)xs4[s & 1][0];
        const ulonglong2* xg1 = (const ulonglong2*)xs4[s & 1][1];
        const ulonglong2* wp  = (const ulonglong2*)(wq + s * 72);

        #pragma unroll
        for (int dj = 0; dj < 3; ++dj) {
            ulonglong2 xlo[4], xhi[4];
            #pragma unroll
            for (int r = 0; r < 4; ++r)
                xlo[r] = xg0[(2 * ty + r) * HALO_W + tx + dj];
            #pragma unroll
            for (int r = 0; r < 4; ++r)
                xhi[r] = xg1[(2 * ty + r) * HALO_W + tx + dj];
            #pragma unroll
            for (int di = 0; di < 3; ++di) {
                const ulonglong2* wt = wp + (di * 3 + dj) * 8;
                ulonglong2 w0 = wt[0], w1 = wt[1], w2 = wt[2], w3 = wt[3];
                ulonglong2 w4 = wt[4], w5 = wt[5], w6 = wt[6], w7 = wt[7];
                FMA2(A0, xlo[di].x, w0.x); FMA2(A1, xlo[di].x, w0.y);
                FMA2(A2, xlo[di].x, w1.x); FMA2(A3, xlo[di].x, w1.y);
                FMA2(B0, xlo[di+1].x, w0.x); FMA2(B1, xlo[di+1].x, w0.y);
                FMA2(B2, xlo[di+1].x, w1.x); FMA2(B3, xlo[di+1].x, w1.y);
                FMA2(A0, xlo[di].y, w2.x); FMA2(A1, xlo[di].y, w2.y);
                FMA2(A2, xlo[di].y, w3.x); FMA2(A3, xlo[di].y, w3.y);
                FMA2(B0, xlo[di+1].y, w2.x); FMA2(B1, xlo[di+1].y, w2.y);
                FMA2(B2, xlo[di+1].y, w3.x); FMA2(B3, xlo[di+1].y, w3.y);
                FMA2(A0, xhi[di].x, w4.x); FMA2(A1, xhi[di].x, w4.y);
                FMA2(A2, xhi[di].x, w5.x); FMA2(A3, xhi[di].x, w5.y);
                FMA2(B0, xhi[di+1].x, w4.x); FMA2(B1, xhi[di+1].x, w4.y);
                FMA2(B2, xhi[di+1].x, w5.x); FMA2(B3, xhi[di+1].x, w5.y);
                FMA2(A0, xhi[di].y, w6.x); FMA2(A1, xhi[di].y, w6.y);
                FMA2(A2, xhi[di].y, w7.x); FMA2(A3, xhi[di].y, w7.y);
                FMA2(B0, xhi[di+1].y, w6.x); FMA2(B1, xhi[di+1].y, w6.y);
                FMA2(B2, xhi[di+1].y, w7.x); FMA2(B3, xhi[di+1].y, w7.y);
            }
        }
    }

    // Reduce packed accumulators -> angles, run circuit, store duplicated ez.
    {
        float lo, hi, a0, a1, a2, a3;
        asm("mov.b64 {%0, %1}, %2;" : "=f"(lo), "=f"(hi) : "l"(A0)); a0 = lo + hi;
        asm("mov.b64 {%0, %1}, %2;" : "=f"(lo), "=f"(hi) : "l"(A1)); a1 = lo + hi;
        asm("mov.b64 {%0, %1}, %2;" : "=f"(lo), "=f"(hi) : "l"(A2)); a2 = lo + hi;
        asm("mov.b64 {%0, %1}, %2;" : "=f"(lo), "=f"(hi) : "l"(A3)); a3 = lo + hi;
        float4 eA = quantum_ez(sgates, a0, a1, a2, a3);
        int lpA = (2 * ty) * TW + tx;
        ezd[lpA * 2 + 0] = make_float4(eA.x, eA.x, eA.y, eA.y);
        ezd[lpA * 2 + 1] = make_float4(eA.z, eA.z, eA.w, eA.w);
        asm("mov.b64 {%0, %1}, %2;" : "=f"(lo), "=f"(hi) : "l"(B0)); a0 = lo + hi;
        asm("mov.b64 {%0, %1}, %2;" : "=f"(lo), "=f"(hi) : "l"(B1)); a1 = lo + hi;
        asm("mov.b64 {%0, %1}, %2;" : "=f"(lo), "=f"(hi) : "l"(B2)); a2 = lo + hi;
        asm("mov.b64 {%0, %1}, %2;" : "=f"(lo), "=f"(hi) : "l"(B3)); a3 = lo + hi;
        float4 eB = quantum_ez(sgates, a0, a1, a2, a3);
        int lpB = (2 * ty + 1) * TW + tx;
        ezd[lpB * 2 + 0] = make_float4(eB.x, eB.x, eB.y, eB.y);
        ezd[lpB * 2 + 1] = make_float4(eB.z, eB.z, eB.w, eB.w);
    }
    __syncthreads();

    // ---------------- coalesced FC epilogue (f32x2-packed, no packs in loop) ----
    const int lane = t & 31;
    const int wi   = t >> 5;
    const float4* fw4 = (const float4*)fcw;
    float4 fr0 = fw4[4 * lane + 0];
    float4 fr1 = fw4[4 * lane + 1];
    float4 fr2 = fw4[4 * lane + 2];
    float4 fr3 = fw4[4 * lane + 3];
    float4 bb4 = ((const float4*)fcb)[lane];

    unsigned long long w01k0, w01k1, w01k2, w01k3;  // (fcw[c0][k], fcw[c1][k])
    unsigned long long w23k0, w23k1, w23k2, w23k3;
    unsigned long long bias01, bias23;
    PACK2(w01k0, fr0.x, fr1.x); PACK2(w01k1, fr0.y, fr1.y);
    PACK2(w01k2, fr0.z, fr1.z); PACK2(w01k3, fr0.w, fr1.w);
    PACK2(w23k0, fr2.x, fr3.x); PACK2(w23k1, fr2.y, fr3.y);
    PACK2(w23k2, fr2.z, fr3.z); PACK2(w23k3, fr2.w, fr3.w);
    PACK2(bias01, bb4.x, bb4.y); PACK2(bias23, bb4.z, bb4.w);

    const ulonglong2* ezp = (const ulonglong2*)ezd;
    ulonglong2* ob = (ulonglong2*)out + (size_t)b * 4096 * 32;
    #pragma unroll 4
    for (int j = 0; j < 64; ++j) {
        const int lp = wi * 64 + j;
        ulonglong2 e01 = ezp[lp * 2 + 0];   // (e0,e0),(e1,e1)
        ulonglong2 e23 = ezp[lp * 2 + 1];   // (e2,e2),(e3,e3)
        unsigned long long acc01, acc23;
        FMA2N(acc01, w01k0, e01.x, bias01);
        FMA2N(acc23, w23k0, e01.x, bias23);
        FMA2(acc01, w01k1, e01.y); FMA2(acc23, w23k1, e01.y);
        FMA2(acc01, w01k2, e23.x); FMA2(acc23, w23k2, e23.x);
        FMA2(acc01, w01k3, e23.y); FMA2(acc23, w23k3, e23.y);
        const int py = h0 + (lp >> 4);
        const int px = w0 + (lp & 15);
        ulonglong2 o2; o2.x = acc01; o2.y = acc23;
        ob[(size_t)(py * WW + px) * 32 + lane] = o2;
    }
}

extern "C" void kernel_launch(void* const* d_in, const int* in_sizes, int n_in,
                              void* d_out, int out_size)
{
    (void)in_sizes; (void)n_in; (void)out_size;
    const float* x    = (const float*)d_in[0];
    const float* fc1w = (const float*)d_in[1];
    const float* fc1b = (const float*)d_in[2];
    const float* u3p  = (const float*)d_in[3];
    const float* cu3p = (const float*)d_in[4];
    const float* fcw  = (const float*)d_in[5];
    const float* fcb  = (const float*)d_in[6];
    float* out = (float*)d_out;

    dim3 grid(WW / TW, HH / TH, 16);
    qconv_kernel<<<grid, NTHR>>>(x, fc1w, fc1b, u3p, cu3p, fcw, fcb, out);
}

// round 8
// speedup vs baseline: 1.1008x; 1.0122x over previous
#include <cuda_runtime.h>

#define NQ    4
#define CIN   64
#define HH    64
#define WW    64
#define OUTC  128
#define TH    16
#define TW    16
#define NTHR  128
#define HALO_H (TH + 2)
#define HALO_W (TW + 2)
#define HALO_N (HALO_H * HALO_W)   // 324

#define FMA2(acc, a, b) \
    asm("fma.rn.f32x2 %0, %1, %2, %0;" : "+l"(acc) : "l"(a), "l"(b))
#define FMA2N(d, a, b, c) \
    asm("fma.rn.f32x2 %0, %1, %2, %3;" : "=l"(d) : "l"(a), "l"(b), "l"(c))
#define PACK2(d, lo, hi) \
    asm("mov.b64 %0, {%1, %2};" : "=l"(d) : "f"(lo), "f"(hi))

// Full 4-qubit circuit from the 4 angles -> <Z> per wire. Gates in smem.
__device__ __forceinline__ float4 quantum_ez(const float* __restrict__ sg,
                                             float a0, float a1, float a2, float a3)
{
    float S[NQ][4];
    float angs[NQ] = {a0, a1, a2, a3};
    #pragma unroll
    for (int q = 0; q < NQ; ++q) {
        float st, ct;
        __sincosf(0.5f * angs[q], &st, &ct);
        const float* m = sg + q * 8;
        S[q][0] = m[0] * ct + m[2] * st;
        S[q][1] = m[1] * ct + m[3] * st;
        S[q][2] = m[4] * ct + m[6] * st;
        S[q][3] = m[5] * ct + m[7] * st;
    }

    float q01r[4], q01i[4], q23r[4], q23i[4];
    #pragma unroll
    for (int i0 = 0; i0 < 2; ++i0)
        #pragma unroll
        for (int i1 = 0; i1 < 2; ++i1) {
            float xr = S[0][i0 * 2], xi = S[0][i0 * 2 + 1];
            float yr = S[1][i1 * 2], yi = S[1][i1 * 2 + 1];
            q01r[i0 * 2 + i1] = xr * yr - xi * yi;
            q01i[i0 * 2 + i1] = xr * yi + xi * yr;
            xr = S[2][i0 * 2]; xi = S[2][i0 * 2 + 1];
            yr = S[3][i1 * 2]; yi = S[3][i1 * 2 + 1];
            q23r[i0 * 2 + i1] = xr * yr - xi * yi;
            q23i[i0 * 2 + i1] = xr * yi + xi * yr;
        }

    float pr[16], pi[16];
    #pragma unroll
    for (int u = 0; u < 4; ++u)
        #pragma unroll
        for (int v = 0; v < 4; ++v) {
            pr[u * 4 + v] = q01r[u] * q23r[v] - q01i[u] * q23i[v];
            pi[u * 4 + v] = q01r[u] * q23i[v] + q01i[u] * q23r[v];
        }

    #pragma unroll
    for (int g = 0; g < 4; ++g) {
        const float* U = sg + 32 + g * 8;
        float u00r = U[0], u00i = U[1], u01r = U[2], u01i = U[3];
        float u10r = U[4], u10i = U[5], u11r = U[6], u11i = U[7];
        const int bc = 8 >> g;
        const int bt = 8 >> ((g + 1) & 3);
        #pragma unroll
        for (int i = 0; i < 16; ++i) {
            if ((i & bc) && !(i & bt)) {
                const int j = i | bt;
                float x0r = pr[i], x0i = pi[i], x1r = pr[j], x1i = pi[j];
                pr[i] = u00r * x0r - u00i * x0i + u01r * x1r - u01i * x1i;
                pi[i] = u00r * x0i + u00i * x0r + u01r * x1i + u01i * x1r;
                pr[j] = u10r * x0r - u10i * x0i + u11r * x1r - u11i * x1i;
                pi[j] = u10r * x0i + u10i * x0r + u11r * x1i + u11i * x1r;
            }
        }
    }

    float e0 = 0.f, e1 = 0.f, e2 = 0.f, e3 = 0.f;
    #pragma unroll
    for (int i = 0; i < 16; ++i) {
        float pp = pr[i] * pr[i] + pi[i] * pi[i];
        e0 += (i & 8) ? -pp : pp;
        e1 += (i & 4) ? -pp : pp;
        e2 += (i & 2) ? -pp : pp;
        e3 += (i & 1) ? -pp : pp;
    }
    return make_float4(e0, e1, e2, e3);
}

__global__ __launch_bounds__(NTHR, 2)
void qconv_kernel(const float* __restrict__ x,     // (16,64,64,64)
                  const float* __restrict__ fc1w,  // (4,576)
                  const float* __restrict__ fc1b,  // (4,)
                  const float* __restrict__ u3p,   // (4,3)
                  const float* __restrict__ cu3p,  // (4,3)
                  const float* __restrict__ fcw,   // (128,4)
                  const float* __restrict__ fcb,   // (128,)
                  float* __restrict__ out)         // (16,4096,128) flat
{
    __shared__ float4 wq[576];            // packed conv weights (f32x2 pairs)
    __shared__ float4 xs4[2][2][HALO_N];  // [buf][chan-group][pos] 4 channels/float4
    __shared__ float4 ezd[TH * TW * 2];   // duplicated <Z>: (e0,e0,e1,e1)(e2,e2,e3,e3)
    __shared__ float  sgates[64];         // [0..31] U3, [32..63] CU3

    const int t  = threadIdx.x;
    const int b  = blockIdx.z;
    const int h0 = blockIdx.y * TH;
    const int w0 = blockIdx.x * TW;

    // ---- per-block setup ----
    if (t < 8) {
        const float* p = (t < 4) ? (u3p + t * 3) : (cu3p + (t - 4) * 3);
        float th = p[0], ph = p[1], la = p[2];
        float st, ct;   __sincosf(0.5f * th, &st, &ct);
        float sl, cl;   __sincosf(la, &sl, &cl);
        float sp, cp;   __sincosf(ph, &sp, &cp);
        float spl, cpl; __sincosf(ph + la, &spl, &cpl);
        float* o = sgates + t * 8;
        o[0] = ct;        o[1] = 0.f;
        o[2] = -cl * st;  o[3] = -sl * st;
        o[4] = cp * st;   o[5] = sp * st;
        o[6] = cpl * ct;  o[7] = spl * ct;
    }
    // Packed weight table: wq[s*72 + tap*8 + p*2 + h] =
    //   (w[c0][2h], w[c1][2h], w[c0][2h+1], w[c1][2h+1]), c0 = s*8+2p.
    #pragma unroll
    for (int f = t; f < 576; f += NTHR) {
        int h   = f & 1;
        int p   = (f >> 1) & 3;
        int tap = (f >> 3) % 9;
        int s   = f / 72;
        int c0  = s * 8 + 2 * p;
        int oa  = 2 * h, ob = 2 * h + 1;
        wq[f] = make_float4(fc1w[oa * 576 + c0 * 9 + tap],
                            fc1w[oa * 576 + (c0 + 1) * 9 + tap],
                            fc1w[ob * 576 + c0 * 9 + tap],
                            fc1w[ob * 576 + (c0 + 1) * 9 + tap]);
    }

    const int ty = t >> 4;   // 0..7  (handles pixel rows 2ty, 2ty+1)
    const int tx = t & 15;   // 0..15
    const int by = h0 - 1, bx = w0 - 1;

    // ---- channel-invariant halo staging: 3 slots/thread over 324 positions ----
    const int i0 = t, i1 = t + NTHR, i2 = t + 2 * NTHR;
    const bool has2 = (i2 < HALO_N);
    const int r0 = i0 / HALO_W, c0s = i0 - r0 * HALO_W;
    const int r1 = i1 / HALO_W, c1s = i1 - r1 * HALO_W;
    const int r2 = has2 ? i2 / HALO_W : 0, c2s = has2 ? (i2 - r2 * HALO_W) : 0;

    int gy, gx;
    gy = by + r0; gx = bx + c0s;
    const bool va0 = (unsigned)gy < (unsigned)HH && (unsigned)gx < (unsigned)WW;
    const float* cur0 = x + ((size_t)b * CIN) * (HH * WW) + (va0 ? gy * WW + gx : 0);
    gy = by + r1; gx = bx + c1s;
    const bool va1 = (unsigned)gy < (unsigned)HH && (unsigned)gx < (unsigned)WW;
    const float* cur1 = x + ((size_t)b * CIN) * (HH * WW) + (va1 ? gy * WW + gx : 0);
    gy = by + r2; gx = bx + c2s;
    const bool va2 = has2 && (unsigned)gy < (unsigned)HH && (unsigned)gx < (unsigned)WW;
    const float* cur2 = x + ((size_t)b * CIN) * (HH * WW) + (va2 ? gy * WW + gx : 0);

    // Prologue: load channel-group 0 into registers.
    float v0[8], v1[8], v2[8];
    #pragma unroll
    for (int k = 0; k < 8; ++k) v0[k] = va0 ? cur0[k * (HH * WW)] : 0.f;
    #pragma unroll
    for (int k = 0; k < 8; ++k) v1[k] = va1 ? cur1[k * (HH * WW)] : 0.f;
    #pragma unroll
    for (int k = 0; k < 8; ++k) v2[k] = va2 ? cur2[k * (HH * WW)] : 0.f;
    cur0 += 8 * HH * WW; cur1 += 8 * HH * WW; cur2 += 8 * HH * WW;

    // 8 packed accumulators: A = pixel row 2ty, B = pixel row 2ty+1.
    unsigned long long A0, A1, A2, A3, B0, B1, B2, B3;
    {
        float z = 0.f;
        float b0 = fc1b[0], b1 = fc1b[1], b2 = fc1b[2], b3 = fc1b[3];
        PACK2(A0, b0, z); PACK2(A1, b1, z); PACK2(A2, b2, z); PACK2(A3, b3, z);
        PACK2(B0, b0, z); PACK2(B1, b1, z); PACK2(B2, b2, z); PACK2(B3, b3, z);
    }

    const int hbase = (2 * ty) * HALO_W + tx;

    // Single-barrier-per-stage double-buffered loop:
    //   STS(s) -> [LDG(s+1)] -> barrier -> compute(s)
    for (int s = 0; s < 8; ++s) {
        {
            float4* d0 = xs4[s & 1][0];
            float4* d1 = xs4[s & 1][1];
            d0[i0] = make_float4(v0[0], v0[1], v0[2], v0[3]);
            d1[i0] = make_float4(v0[4], v0[5], v0[6], v0[7]);
            d0[i1] = make_float4(v1[0], v1[1], v1[2], v1[3]);
            d1[i1] = make_float4(v1[4], v1[5], v1[6], v1[7]);
            if (has2) {
                d0[i2] = make_float4(v2[0], v2[1], v2[2], v2[3]);
                d1[i2] = make_float4(v2[4], v2[5], v2[6], v2[7]);
            }
        }
        if (s < 7) {
            #pragma unroll
            for (int k = 0; k < 8; ++k) v0[k] = va0 ? cur0[k * (HH * WW)] : 0.f;
            #pragma unroll
            for (int k = 0; k < 8; ++k) v1[k] = va1 ? cur1[k * (HH * WW)] : 0.f;
            #pragma unroll
            for (int k = 0; k < 8; ++k) v2[k] = va2 ? cur2[k * (HH * WW)] : 0.f;
            cur0 += 8 * HH * WW; cur1 += 8 * HH * WW; cur2 += 8 * HH * WW;
        }
        __syncthreads();

        const ulonglong2* xg0 = (const ulonglong2*)xs4[s & 1][0];
        const ulonglong2* xg1 = (const ulonglong2*)xs4[s & 1][1];
        const ulonglong2* wp  = (const ulonglong2*)(wq + s * 72);

        // Software-pipelined columns: prefetch column dj+1 while computing dj.
        ulonglong2 xlo[4], xhi[4], ylo[4], yhi[4];
        #pragma unroll
        for (int r = 0; r < 4; ++r) xlo[r] = xg0[hbase + r * HALO_W];
        #pragma unroll
        for (int r = 0; r < 4; ++r) xhi[r] = xg1[hbase + r * HALO_W];

        #pragma unroll
        for (int dj = 0; dj < 3; ++dj) {
            if (dj < 2) {
                #pragma unroll
                for (int r = 0; r < 4; ++r) ylo[r] = xg0[hbase + dj + 1 + r * HALO_W];
                #pragma unroll
                for (int r = 0; r < 4; ++r) yhi[r] = xg1[hbase + dj + 1 + r * HALO_W];
            }
            #pragma unroll
            for (int di = 0; di < 3; ++di) {
                const ulonglong2* wt = wp + (di * 3 + dj) * 8;
                ulonglong2 w0 = wt[0], w1 = wt[1], w2 = wt[2], w3 = wt[3];
                ulonglong2 w4 = wt[4], w5 = wt[5], w6 = wt[6], w7 = wt[7];
                FMA2(A0, xlo[di].x, w0.x); FMA2(A1, xlo[di].x, w0.y);
                FMA2(A2, xlo[di].x, w1.x); FMA2(A3, xlo[di].x, w1.y);
                FMA2(B0, xlo[di+1].x, w0.x); FMA2(B1, xlo[di+1].x, w0.y);
                FMA2(B2, xlo[di+1].x, w1.x); FMA2(B3, xlo[di+1].x, w1.y);
                FMA2(A0, xlo[di].y, w2.x); FMA2(A1, xlo[di].y, w2.y);
                FMA2(A2, xlo[di].y, w3.x); FMA2(A3, xlo[di].y, w3.y);
                FMA2(B0, xlo[di+1].y, w2.x); FMA2(B1, xlo[di+1].y, w2.y);
                FMA2(B2, xlo[di+1].y, w3.x); FMA2(B3, xlo[di+1].y, w3.y);
                FMA2(A0, xhi[di].x, w4.x); FMA2(A1, xhi[di].x, w4.y);
                FMA2(A2, xhi[di].x, w5.x); FMA2(A3, xhi[di].x, w5.y);
                FMA2(B0, xhi[di+1].x, w4.x); FMA2(B1, xhi[di+1].x, w4.y);
                FMA2(B2, xhi[di+1].x, w5.x); FMA2(B3, xhi[di+1].x, w5.y);
                FMA2(A0, xhi[di].y, w6.x); FMA2(A1, xhi[di].y, w6.y);
                FMA2(A2, xhi[di].y, w7.x); FMA2(A3, xhi[di].y, w7.y);
                FMA2(B0, xhi[di+1].y, w6.x); FMA2(B1, xhi[di+1].y, w6.y);
                FMA2(B2, xhi[di+1].y, w7.x); FMA2(B3, xhi[di+1].y, w7.y);
            }
            if (dj < 2) {
                #pragma unroll
                for (int r = 0; r < 4; ++r) { xlo[r] = ylo[r]; xhi[r] = yhi[r]; }
            }
        }
    }

    // Reduce packed accumulators -> angles, run circuit, store duplicated ez.
    {
        float lo, hi, a0, a1, a2, a3;
        asm("mov.b64 {%0, %1}, %2;" : "=f"(lo), "=f"(hi) : "l"(A0)); a0 = lo + hi;
        asm("mov.b64 {%0, %1}, %2;" : "=f"(lo), "=f"(hi) : "l"(A1)); a1 = lo + hi;
        asm("mov.b64 {%0, %1}, %2;" : "=f"(lo), "=f"(hi) : "l"(A2)); a2 = lo + hi;
        asm("mov.b64 {%0, %1}, %2;" : "=f"(lo), "=f"(hi) : "l"(A3)); a3 = lo + hi;
        float4 eA = quantum_ez(sgates, a0, a1, a2, a3);
        int lpA = (2 * ty) * TW + tx;
        ezd[lpA * 2 + 0] = make_float4(eA.x, eA.x, eA.y, eA.y);
        ezd[lpA * 2 + 1] = make_float4(eA.z, eA.z, eA.w, eA.w);
        asm("mov.b64 {%0, %1}, %2;" : "=f"(lo), "=f"(hi) : "l"(B0)); a0 = lo + hi;
        asm("mov.b64 {%0, %1}, %2;" : "=f"(lo), "=f"(hi) : "l"(B1)); a1 = lo + hi;
        asm("mov.b64 {%0, %1}, %2;" : "=f"(lo), "=f"(hi) : "l"(B2)); a2 = lo + hi;
        asm("mov.b64 {%0, %1}, %2;" : "=f"(lo), "=f"(hi) : "l"(B3)); a3 = lo + hi;
        float4 eB = quantum_ez(sgates, a0, a1, a2, a3);
        int lpB = (2 * ty + 1) * TW + tx;
        ezd[lpB * 2 + 0] = make_float4(eB.x, eB.x, eB.y, eB.y);
        ezd[lpB * 2 + 1] = make_float4(eB.z, eB.z, eB.w, eB.w);
    }
    __syncthreads();

    // ---------------- coalesced FC epilogue (f32x2-packed, no packs in loop) ----
    const int lane = t & 31;
    const int wi   = t >> 5;
    const float4* fw4 = (const float4*)fcw;
    float4 fr0 = fw4[4 * lane + 0];
    float4 fr1 = fw4[4 * lane + 1];
    float4 fr2 = fw4[4 * lane + 2];
    float4 fr3 = fw4[4 * lane + 3];
    float4 bb4 = ((const float4*)fcb)[lane];

    unsigned long long w01k0, w01k1, w01k2, w01k3;  // (fcw[c0][k], fcw[c1][k])
    unsigned long long w23k0, w23k1, w23k2, w23k3;
    unsigned long long bias01, bias23;
    PACK2(w01k0, fr0.x, fr1.x); PACK2(w01k1, fr0.y, fr1.y);
    PACK2(w01k2, fr0.z, fr1.z); PACK2(w01k3, fr0.w, fr1.w);
    PACK2(w23k0, fr2.x, fr3.x); PACK2(w23k1, fr2.y, fr3.y);
    PACK2(w23k2, fr2.z, fr3.z); PACK2(w23k3, fr2.w, fr3.w);
    PACK2(bias01, bb4.x, bb4.y); PACK2(bias23, bb4.z, bb4.w);

    const ulonglong2* ezp = (const ulonglong2*)ezd;
    ulonglong2* ob = (ulonglong2*)out + (size_t)b * 4096 * 32;
    #pragma unroll 4
    for (int j = 0; j < 64; ++j) {
        const int lp = wi * 64 + j;
        ulonglong2 e01 = ezp[lp * 2 + 0];   // (e0,e0),(e1,e1)
        ulonglong2 e23 = ezp[lp * 2 + 1];   // (e2,e2),(e3,e3)
        unsigned long long acc01, acc23;
        FMA2N(acc01, w01k0, e01.x, bias01);
        FMA2N(acc23, w23k0, e01.x, bias23);
        FMA2(acc01, w01k1, e01.y); FMA2(acc23, w23k1, e01.y);
        FMA2(acc01, w01k2, e23.x); FMA2(acc23, w23k2, e23.x);
        FMA2(acc01, w01k3, e23.y); FMA2(acc23, w23k3, e23.y);
        const int py = h0 + (lp >> 4);
        const int px = w0 + (lp & 15);
        ulonglong2 o2; o2.x = acc01; o2.y = acc23;
        ob[(size_t)(py * WW + px) * 32 + lane] = o2;
    }
}

extern "C" void kernel_launch(void* const* d_in, const int* in_sizes, int n_in,
                              void* d_out, int out_size)
{
    (void)in_sizes; (void)n_in; (void)out_size;
    const float* x    = (const float*)d_in[0];
    const float* fc1w = (const float*)d_in[1];
    const float* fc1b = (const float*)d_in[2];
    const float* u3p  = (const float*)d_in[3];
    const float* cu3p = (const float*)d_in[4];
    const float* fcw  = (const float*)d_in[5];
    const float* fcb  = (const float*)d_in[6];
    float* out = (float*)d_out;

    dim3 grid(WW / TW, HH / TH, 16);
    qconv_kernel<<<grid, NTHR>>>(x, fc1w, fc1b, u3p, cu3p, fcw, fcb, out);
}